// round 10
// baseline (speedup 1.0000x reference)
#include <cuda_runtime.h>

#define NN    8192
#define MAXO  300
#define CH    2048        // chunk size for chunk_sort
#define CT    256         // chunk_sort threads (EPB 8)
#define MT    1024        // merge threads (EPB 8)

typedef unsigned long long u64;

// Static device scratch (no allocation). Fully rewritten every launch.
__device__ u64    g_keys[NN];
__device__ float4 g_boxes[NN];
__device__ float  g_area[NN];
__device__ int    g_sidx[NN];

__device__ __forceinline__ void cmpex(u64& a, u64& b, bool up) {
  u64 x = a, y = b;
  if ((x > y) == up) { a = y; b = x; }
}

// exact decision: IoU(i,j) > 0.5 with IEEE divide semantics
__device__ __forceinline__ bool iou_gt(float4 bi, float ai, float4 bj, float aj) {
  float lx = fmaxf(bi.x, bj.x);
  float ly = fmaxf(bi.y, bj.y);
  float rx = fminf(bi.z, bj.z);
  float ry = fminf(bi.w, bj.w);
  float w  = fmaxf(__fsub_rn(rx, lx), 0.0f);
  float h  = fmaxf(__fsub_rn(ry, ly), 0.0f);
  float inter = __fmul_rn(w, h);
  float uni   = __fsub_rn(__fadd_rn(ai, aj), inter);
  float d   = __fmaf_rn(-0.5f, uni, inter);
  float tol = 1e-6f * uni;
  bool sup = d > tol;
  if (fabsf(d) <= tol) sup = (__fdiv_rn(inter, uni) > 0.5f);   // rare borderline
  return sup;
}

// ---------------------------------------------------------------------------
// Kernel A1: chunk bitonic sort (unchanged from R9). 4 blocks x 256 threads,
// each sorts a 2048-element chunk running the GLOBAL network's k=2..2048.
// ---------------------------------------------------------------------------
__global__ __launch_bounds__(CT, 1)
void chunk_sort(const float* __restrict__ scores) {
  __shared__ u64 sk[CH];
  const int tid   = threadIdx.x;
  const int cbase = blockIdx.x * CH;
  for (int p = tid; p < CH; p += CT) {
    unsigned sb = __float_as_uint(scores[cbase + p]);  // scores>=0: bits monotone
    sk[p] = (((u64)(~sb)) << 32) | (unsigned)(cbase + p);
  }
  __syncthreads();
  const int lbase = tid * 8;
  const int gbase = cbase + lbase;
  u64 v[8];
#pragma unroll
  for (int e = 0; e < 8; e++) v[e] = sk[lbase + e];

#pragma unroll
  for (int e = 0; e < 8; e++) { int e2 = e ^ 1; if (e2 > e) cmpex(v[e], v[e2], (e & 2) == 0); }
#pragma unroll
  for (int jj = 2; jj; jj >>= 1)
#pragma unroll
    for (int e = 0; e < 8; e++) { int e2 = e ^ jj; if (e2 > e) cmpex(v[e], v[e2], (e & 4) == 0); }
  {
    bool up = ((gbase & 8) == 0);
#pragma unroll
    for (int jj = 4; jj; jj >>= 1)
#pragma unroll
      for (int e = 0; e < 8; e++) { int e2 = e ^ jj; if (e2 > e) cmpex(v[e], v[e2], up); }
  }

  for (int k = 16; k <= CH; k <<= 1) {
    const bool up = ((gbase & k) == 0);
    int jj = k >> 1;
    if (jj >= 256) {
#pragma unroll
      for (int e = 0; e < 8; e++) sk[lbase + e] = v[e];
      __syncthreads();
      for (; jj >= 256; jj >>= 1) {
        for (int pp = tid; pp < CH / 2; pp += CT) {
          int p = ((pp & ~(jj - 1)) << 1) | (pp & (jj - 1));
          int q = p | jj;
          bool u2 = (((cbase + p) & k) == 0);
          u64 a = sk[p], b = sk[q];
          if ((a > b) == u2) { sk[p] = b; sk[q] = a; }
        }
        __syncthreads();
      }
#pragma unroll
      for (int e = 0; e < 8; e++) v[e] = sk[lbase + e];
    }
    for (; jj >= 8; jj >>= 1) {
      int s = jj >> 3;
      bool takemin = (((tid & s) == 0) == up);
#pragma unroll
      for (int e = 0; e < 8; e++) {
        u64 o  = __shfl_xor_sync(0xFFFFFFFFu, v[e], s);
        u64 mn = (v[e] < o) ? v[e] : o;
        u64 mx = (v[e] < o) ? o : v[e];
        v[e] = takemin ? mn : mx;
      }
    }
#pragma unroll
    for (int j2 = 4; j2; j2 >>= 1)
#pragma unroll
      for (int e = 0; e < 8; e++) { int e2 = e ^ j2; if (e2 > e) cmpex(v[e], v[e2], up); }
  }
#pragma unroll
  for (int e = 0; e < 8; e++) g_keys[gbase + e] = v[e];
}

// ---------------------------------------------------------------------------
// Kernel A2: bitonic merge phases k=4096, 8192 (unchanged from R9); emits
// sorted boxes/areas/sidx and inits the output to -1.
// ---------------------------------------------------------------------------
__global__ __launch_bounds__(MT, 1)
void merge_kernel(const float4* __restrict__ rois, float* __restrict__ out) {
  extern __shared__ u64 sk[];   // 64KB
  const int tid  = threadIdx.x;
  const int base = tid * 8;
  if (tid < MAXO) out[tid] = -1.0f;
  u64 v[8];
#pragma unroll
  for (int e = 0; e < 8; e++) v[e] = g_keys[base + e];

  for (int k = 2 * CH; k <= NN; k <<= 1) {
    const bool up = ((base & k) == 0);
    int jj = k >> 1;
#pragma unroll
    for (int e = 0; e < 8; e++) sk[base + e] = v[e];
    __syncthreads();
    for (; jj >= 256; jj >>= 1) {
      for (int pp = tid; pp < NN / 2; pp += MT) {
        int p = ((pp & ~(jj - 1)) << 1) | (pp & (jj - 1));
        int q = p | jj;
        bool u2 = ((p & k) == 0);
        u64 a = sk[p], b = sk[q];
        if ((a > b) == u2) { sk[p] = b; sk[q] = a; }
      }
      __syncthreads();
    }
#pragma unroll
    for (int e = 0; e < 8; e++) v[e] = sk[base + e];
    for (; jj >= 8; jj >>= 1) {
      int s = jj >> 3;
      bool takemin = (((tid & s) == 0) == up);
#pragma unroll
      for (int e = 0; e < 8; e++) {
        u64 o  = __shfl_xor_sync(0xFFFFFFFFu, v[e], s);
        u64 mn = (v[e] < o) ? v[e] : o;
        u64 mx = (v[e] < o) ? o : v[e];
        v[e] = takemin ? mn : mx;
      }
    }
#pragma unroll
    for (int j2 = 4; j2; j2 >>= 1)
#pragma unroll
      for (int e = 0; e < 8; e++) { int e2 = e ^ j2; if (e2 > e) cmpex(v[e], v[e2], up); }
  }

#pragma unroll
  for (int e = 0; e < 8; e++) {
    int p  = base + e;
    int id = (int)(unsigned)(v[e] & 0xFFFFFFFFull);
    g_sidx[p] = id;
    float4 bb = rois[id];
    g_boxes[p] = bb;
    g_area[p] = __fmul_rn(__fsub_rn(bb.z, bb.x), __fsub_rn(bb.w, bb.y));
  }
}

// ---------------------------------------------------------------------------
// Kernel B: single-warp KEPT-LIST greedy (no precomputed mask).
// Batch = 32 consecutive sorted positions, lane = candidate. Per batch:
//  1) lane tests its candidate vs the kept list in smem (broadcast LDS);
//  2) intra-batch 32x32 IoU matrix from smem-staged candidates;
//  3) ballot resolution (exact serial-greedy semantics);
//  4) kept candidates appended to the list + outputs written.
// Total IoU work ~ candidates x kept ~ 55K (vs 33.5M for the mask).
// ---------------------------------------------------------------------------
__global__ void greedy_kernel(float* __restrict__ out) {
  __shared__ float4 kb[MAXO + 32];     // kept boxes
  __shared__ float  ka[MAXO + 32];     // kept areas
  __shared__ float4 cb[32];            // batch candidate boxes
  __shared__ float  ca[32];
  const int lane = threadIdx.x;
  const unsigned FULL = 0xFFFFFFFFu;
  int K = 0;                           // kept count == outputs written

  for (int p = 0; p < NN && K < MAXO; p += 32) {
    float4 b  = g_boxes[p + lane];     // coalesced
    float  a  = g_area[p + lane];
    int   sid = g_sidx[p + lane];
    cb[lane] = b; ca[lane] = a;
    __syncwarp();

    // 1) vs kept list (independent iterations -> pipelined)
    bool sup = false;
#pragma unroll 4
    for (int k = 0; k < K; k++)
      sup |= iou_gt(b, a, kb[k], ka[k]);

    // 2) intra-batch matrix: bit m = "candidate m suppresses me", m < lane
    unsigned S = 0;
#pragma unroll 4
    for (int m = 0; m < 32; m++)
      S |= ((unsigned)iou_gt(b, a, cb[m], ca[m])) << m;
    S &= (1u << lane) - 1u;

    // 3) ballot resolution (uniform loop; steps = keeps in batch)
    unsigned rest = __ballot_sync(FULL, !sup);
    unsigned kept = 0;
    while (rest) {
      int m = __ffs(rest) - 1;
      kept |= 1u << m;
      unsigned supm = __ballot_sync(FULL, (S >> m) & 1u);
      rest &= ~(supm | (1u << m));
    }

    // 4) append + emit
    if ((kept >> lane) & 1u) {
      int slot = K + __popc(kept & ((1u << lane) - 1u));
      kb[slot] = b; ka[slot] = a;
      if (slot < MAXO) out[slot] = (float)sid;
    }
    K += __popc(kept);
    __syncwarp();                      // kb/cb visible before next batch
  }
}

// ---------------------------------------------------------------------------
extern "C" void kernel_launch(void* const* d_in, const int* in_sizes, int n_in,
                              void* d_out, int out_size) {
  const void* a0 = d_in[0];
  const void* a1 = d_in[1];
  const float4* rois;
  const float*  scores;
  if (in_sizes[0] >= in_sizes[1]) { rois = (const float4*)a0; scores = (const float*)a1; }
  else                            { rois = (const float4*)a1; scores = (const float*)a0; }

  const int merge_smem = NN * (int)sizeof(u64);                 // 64KB
  cudaFuncSetAttribute(merge_kernel, cudaFuncAttributeMaxDynamicSharedMemorySize,
                       merge_smem);

  chunk_sort<<<NN / CH, CT>>>(scores);
  merge_kernel<<<1, MT, merge_smem>>>(rois, (float*)d_out);
  greedy_kernel<<<1, 32>>>((float*)d_out);
}

// round 11
// speedup vs baseline: 2.0376x; 2.0376x over previous
#include <cuda_runtime.h>

#define NN    8192
#define MAXO  300
#define CH    2048        // chunk size for chunk_sort
#define CT    256         // chunk_sort threads (EPB 8)
#define MT    1024        // merge threads (EPB 8)
#define GT    1024        // greedy threads (32 warps)

typedef unsigned long long u64;

// Static device scratch (no allocation). Fully rewritten every launch.
__device__ u64    g_keys[NN];
__device__ float4 g_boxes[NN];
__device__ float  g_area[NN];
__device__ int    g_sidx[NN];

__device__ __forceinline__ void cmpex(u64& a, u64& b, bool up) {
  u64 x = a, y = b;
  if ((x > y) == up) { a = y; b = x; }
}

// exact decision: IoU(i,j) > 0.5 with IEEE divide semantics
__device__ __forceinline__ bool iou_gt(float4 bi, float ai, float4 bj, float aj) {
  float lx = fmaxf(bi.x, bj.x);
  float ly = fmaxf(bi.y, bj.y);
  float rx = fminf(bi.z, bj.z);
  float ry = fminf(bi.w, bj.w);
  float w  = fmaxf(__fsub_rn(rx, lx), 0.0f);
  float h  = fmaxf(__fsub_rn(ry, ly), 0.0f);
  float inter = __fmul_rn(w, h);
  float uni   = __fsub_rn(__fadd_rn(ai, aj), inter);
  float d   = __fmaf_rn(-0.5f, uni, inter);
  float tol = 1e-6f * uni;
  bool sup = d > tol;
  if (fabsf(d) <= tol) sup = (__fdiv_rn(inter, uni) > 0.5f);   // rare borderline
  return sup;
}

// ---------------------------------------------------------------------------
// Kernel A1: chunk bitonic sort (unchanged). 4 blocks x 256 threads, each
// sorts a 2048-element chunk running the GLOBAL network's phases k=2..2048.
// ---------------------------------------------------------------------------
__global__ __launch_bounds__(CT, 1)
void chunk_sort(const float* __restrict__ scores) {
  __shared__ u64 sk[CH];
  const int tid   = threadIdx.x;
  const int cbase = blockIdx.x * CH;
  for (int p = tid; p < CH; p += CT) {
    unsigned sb = __float_as_uint(scores[cbase + p]);  // scores>=0: bits monotone
    sk[p] = (((u64)(~sb)) << 32) | (unsigned)(cbase + p);
  }
  __syncthreads();
  const int lbase = tid * 8;
  const int gbase = cbase + lbase;
  u64 v[8];
#pragma unroll
  for (int e = 0; e < 8; e++) v[e] = sk[lbase + e];

#pragma unroll
  for (int e = 0; e < 8; e++) { int e2 = e ^ 1; if (e2 > e) cmpex(v[e], v[e2], (e & 2) == 0); }
#pragma unroll
  for (int jj = 2; jj; jj >>= 1)
#pragma unroll
    for (int e = 0; e < 8; e++) { int e2 = e ^ jj; if (e2 > e) cmpex(v[e], v[e2], (e & 4) == 0); }
  {
    bool up = ((gbase & 8) == 0);
#pragma unroll
    for (int jj = 4; jj; jj >>= 1)
#pragma unroll
      for (int e = 0; e < 8; e++) { int e2 = e ^ jj; if (e2 > e) cmpex(v[e], v[e2], up); }
  }

  for (int k = 16; k <= CH; k <<= 1) {
    const bool up = ((gbase & k) == 0);
    int jj = k >> 1;
    if (jj >= 256) {
#pragma unroll
      for (int e = 0; e < 8; e++) sk[lbase + e] = v[e];
      __syncthreads();
      for (; jj >= 256; jj >>= 1) {
        for (int pp = tid; pp < CH / 2; pp += CT) {
          int p = ((pp & ~(jj - 1)) << 1) | (pp & (jj - 1));
          int q = p | jj;
          bool u2 = (((cbase + p) & k) == 0);
          u64 a = sk[p], b = sk[q];
          if ((a > b) == u2) { sk[p] = b; sk[q] = a; }
        }
        __syncthreads();
      }
#pragma unroll
      for (int e = 0; e < 8; e++) v[e] = sk[lbase + e];
    }
    for (; jj >= 8; jj >>= 1) {
      int s = jj >> 3;
      bool takemin = (((tid & s) == 0) == up);
#pragma unroll
      for (int e = 0; e < 8; e++) {
        u64 o  = __shfl_xor_sync(0xFFFFFFFFu, v[e], s);
        u64 mn = (v[e] < o) ? v[e] : o;
        u64 mx = (v[e] < o) ? o : v[e];
        v[e] = takemin ? mn : mx;
      }
    }
#pragma unroll
    for (int j2 = 4; j2; j2 >>= 1)
#pragma unroll
      for (int e = 0; e < 8; e++) { int e2 = e ^ j2; if (e2 > e) cmpex(v[e], v[e2], up); }
  }
#pragma unroll
  for (int e = 0; e < 8; e++) g_keys[gbase + e] = v[e];
}

// ---------------------------------------------------------------------------
// Kernel A2: bitonic merge phases k=4096, 8192 (unchanged); emits sorted
// boxes/areas/sidx and inits the output to -1.
// ---------------------------------------------------------------------------
__global__ __launch_bounds__(MT, 1)
void merge_kernel(const float4* __restrict__ rois, float* __restrict__ out) {
  extern __shared__ u64 sk[];   // 64KB
  const int tid  = threadIdx.x;
  const int base = tid * 8;
  if (tid < MAXO) out[tid] = -1.0f;
  u64 v[8];
#pragma unroll
  for (int e = 0; e < 8; e++) v[e] = g_keys[base + e];

  for (int k = 2 * CH; k <= NN; k <<= 1) {
    const bool up = ((base & k) == 0);
    int jj = k >> 1;
#pragma unroll
    for (int e = 0; e < 8; e++) sk[base + e] = v[e];
    __syncthreads();
    for (; jj >= 256; jj >>= 1) {
      for (int pp = tid; pp < NN / 2; pp += MT) {
        int p = ((pp & ~(jj - 1)) << 1) | (pp & (jj - 1));
        int q = p | jj;
        bool u2 = ((p & k) == 0);
        u64 a = sk[p], b = sk[q];
        if ((a > b) == u2) { sk[p] = b; sk[q] = a; }
      }
      __syncthreads();
    }
#pragma unroll
    for (int e = 0; e < 8; e++) v[e] = sk[base + e];
    for (; jj >= 8; jj >>= 1) {
      int s = jj >> 3;
      bool takemin = (((tid & s) == 0) == up);
#pragma unroll
      for (int e = 0; e < 8; e++) {
        u64 o  = __shfl_xor_sync(0xFFFFFFFFu, v[e], s);
        u64 mn = (v[e] < o) ? v[e] : o;
        u64 mx = (v[e] < o) ? o : v[e];
        v[e] = takemin ? mn : mx;
      }
    }
#pragma unroll
    for (int j2 = 4; j2; j2 >>= 1)
#pragma unroll
      for (int e = 0; e < 8; e++) { int e2 = e ^ j2; if (e2 > e) cmpex(v[e], v[e2], up); }
  }

#pragma unroll
  for (int e = 0; e < 8; e++) {
    int p  = base + e;
    int id = (int)(unsigned)(v[e] & 0xFFFFFFFFull);
    g_sidx[p] = id;
    float4 bb = rois[id];
    g_boxes[p] = bb;
    g_area[p] = __fmul_rn(__fsub_rn(bb.z, bb.x), __fsub_rn(bb.w, bb.y));
  }
}

// ---------------------------------------------------------------------------
// Kernel B: BLOCK-PARALLEL kept-list greedy (1024 threads, 32 warps).
// Batch = 32 consecutive sorted positions; thread (w, lane):
//  - vs-kept: candidate `lane` vs kept slice k = w, w+32, ... -> warp ballot
//  - intra-batch: warp w computes matrix row w (1 IoU/thread) -> Sball[w],
//    which is EXACTLY the suppression word the resolution loop needs.
//  - thread 0 runs the scalar greedy resolution (steps = keeps in batch).
// Decision function identical to serial greedy -> bit-exact keeps.
// ---------------------------------------------------------------------------
__global__ __launch_bounds__(GT, 1)
void greedy_kernel(float* __restrict__ out) {
  __shared__ float4   kb[MAXO + 32];   // kept boxes
  __shared__ float    ka[MAXO + 32];   // kept areas
  __shared__ float4   cb[32];          // batch candidate boxes
  __shared__ float    ca[32];
  __shared__ int      sidc[32];
  __shared__ unsigned supb[32];        // per-warp vs-kept ballots
  __shared__ unsigned Sball[32];       // intra-batch matrix rows
  __shared__ unsigned keptmask;
  __shared__ int      Ksh;

  const int tid  = threadIdx.x;
  const int w    = tid >> 5;
  const int lane = tid & 31;
  const unsigned FULL = 0xFFFFFFFFu;
  int K = 0;

  for (int p = 0; p < NN; p += 32) {
    // stage candidates
    if (tid < 32) {
      cb[tid]   = g_boxes[p + tid];
      ca[tid]   = g_area[p + tid];
      sidc[tid] = g_sidx[p + tid];
    }
    __syncthreads();

    const float4 b = cb[lane];
    const float  a = ca[lane];

    // vs-kept: strided slice per warp
    bool sup = false;
    for (int k = w; k < K; k += 32)
      sup |= iou_gt(b, a, kb[k], ka[k]);
    unsigned sb = __ballot_sync(FULL, sup);
    // intra-batch row w: does candidate w suppress candidate `lane`?
    unsigned rb = __ballot_sync(FULL, iou_gt(b, a, cb[w], ca[w]));
    if (lane == 0) { supb[w] = sb; Sball[w] = rb; }
    __syncthreads();

    // scalar resolution
    if (tid == 0) {
      unsigned so = 0;
#pragma unroll
      for (int q = 0; q < 32; q++) so |= supb[q];
      unsigned rest = ~so, kept = 0;
      while (rest) {
        int m = __ffs(rest) - 1;
        kept |= 1u << m;
        rest &= ~(Sball[m] | (1u << m));   // extra low bits harmless
      }
      keptmask = kept;
      Ksh = K + __popc(kept);
    }
    __syncthreads();

    const unsigned kept = keptmask;
    if (tid < 32 && ((kept >> tid) & 1u)) {
      int slot = K + __popc(kept & ((1u << tid) - 1u));
      kb[slot] = cb[tid];
      ka[slot] = ca[tid];
      if (slot < MAXO) out[slot] = (float)sidc[tid];
    }
    K = Ksh;
    __syncthreads();                      // kb visible before next vs-kept
    if (K >= MAXO) break;
  }
}

// ---------------------------------------------------------------------------
extern "C" void kernel_launch(void* const* d_in, const int* in_sizes, int n_in,
                              void* d_out, int out_size) {
  const void* a0 = d_in[0];
  const void* a1 = d_in[1];
  const float4* rois;
  const float*  scores;
  if (in_sizes[0] >= in_sizes[1]) { rois = (const float4*)a0; scores = (const float*)a1; }
  else                            { rois = (const float4*)a1; scores = (const float*)a0; }

  const int merge_smem = NN * (int)sizeof(u64);                 // 64KB
  cudaFuncSetAttribute(merge_kernel, cudaFuncAttributeMaxDynamicSharedMemorySize,
                       merge_smem);

  chunk_sort<<<NN / CH, CT>>>(scores);
  merge_kernel<<<1, MT, merge_smem>>>(rois, (float*)d_out);
  greedy_kernel<<<1, GT>>>((float*)d_out);
}

// round 12
// speedup vs baseline: 2.2695x; 1.1138x over previous
#include <cuda_runtime.h>

#define NN    8192
#define MAXO  300
#define CH    2048        // chunk size for chunk_sort
#define CT    512         // chunk_sort threads (EPB 4)
#define MT    1024        // fused kernel threads (merge EPB 8)

typedef unsigned long long u64;

// Static device scratch (no allocation). Fully rewritten every launch.
__device__ u64 g_keys[NN];

__device__ __forceinline__ void cmpex(u64& a, u64& b, bool up) {
  u64 x = a, y = b;
  if ((x > y) == up) { a = y; b = x; }
}

// exact decision: IoU(i,j) > 0.5 with IEEE divide semantics
__device__ __forceinline__ bool iou_gt(float4 bi, float ai, float4 bj, float aj) {
  float lx = fmaxf(bi.x, bj.x);
  float ly = fmaxf(bi.y, bj.y);
  float rx = fminf(bi.z, bj.z);
  float ry = fminf(bi.w, bj.w);
  float w  = fmaxf(__fsub_rn(rx, lx), 0.0f);
  float h  = fmaxf(__fsub_rn(ry, ly), 0.0f);
  float inter = __fmul_rn(w, h);
  float uni   = __fsub_rn(__fadd_rn(ai, aj), inter);
  float d   = __fmaf_rn(-0.5f, uni, inter);
  float tol = 1e-6f * uni;
  bool sup = d > tol;
  if (fabsf(d) <= tol) sup = (__fdiv_rn(inter, uni) > 0.5f);   // rare borderline
  return sup;
}

// ---------------------------------------------------------------------------
// Kernel A: chunk bitonic sort. 4 blocks x 512 threads (EPB 4): each sorts a
// 2048-element chunk, phases k=2..2048 of the GLOBAL network. 16 warps/SM
// hide shfl/LDS latency. jj<=2: reg. jj=4..64: shfl. jj>=128: smem.
// ---------------------------------------------------------------------------
__global__ __launch_bounds__(CT, 1)
void chunk_sort(const float* __restrict__ scores) {
  __shared__ u64 sk[CH];
  const int tid   = threadIdx.x;
  const int cbase = blockIdx.x * CH;
  for (int p = tid; p < CH; p += CT) {
    unsigned sb = __float_as_uint(scores[cbase + p]);  // scores>=0: bits monotone
    sk[p] = (((u64)(~sb)) << 32) | (unsigned)(cbase + p);
  }
  __syncthreads();
  const int lbase = tid * 4;
  const int gbase = cbase + lbase;
  u64 v[4];
#pragma unroll
  for (int e = 0; e < 4; e++) v[e] = sk[lbase + e];

  // k=2 (jj=1): direction from element bit 1
  cmpex(v[0], v[1], true);
  cmpex(v[2], v[3], false);
  // k=4 (jj=2,1): direction uniform per thread (bit2 of global idx)
  {
    bool up = ((gbase & 4) == 0);
    cmpex(v[0], v[2], up); cmpex(v[1], v[3], up);
    cmpex(v[0], v[1], up); cmpex(v[2], v[3], up);
  }

  for (int k = 8; k <= CH; k <<= 1) {
    const bool up = ((gbase & k) == 0);
    int jj = k >> 1;
    if (jj >= 128) {
#pragma unroll
      for (int e = 0; e < 4; e++) sk[lbase + e] = v[e];
      __syncthreads();
      for (; jj >= 128; jj >>= 1) {
        for (int pp = tid; pp < CH / 2; pp += CT) {
          int p = ((pp & ~(jj - 1)) << 1) | (pp & (jj - 1));
          int q = p | jj;
          bool u2 = (((cbase + p) & k) == 0);
          u64 a = sk[p], b = sk[q];
          if ((a > b) == u2) { sk[p] = b; sk[q] = a; }
        }
        __syncthreads();
      }
#pragma unroll
      for (int e = 0; e < 4; e++) v[e] = sk[lbase + e];
    }
    for (; jj >= 4; jj >>= 1) {           // in-warp shfl: s = jj/4 in [1,16]
      int s = jj >> 2;
      bool takemin = (((tid & s) == 0) == up);
#pragma unroll
      for (int e = 0; e < 4; e++) {
        u64 o  = __shfl_xor_sync(0xFFFFFFFFu, v[e], s);
        u64 mn = (v[e] < o) ? v[e] : o;
        u64 mx = (v[e] < o) ? o : v[e];
        v[e] = takemin ? mn : mx;
      }
    }
    cmpex(v[0], v[2], up); cmpex(v[1], v[3], up);   // jj=2
    cmpex(v[0], v[1], up); cmpex(v[2], v[3], up);   // jj=1
  }
#pragma unroll
  for (int e = 0; e < 4; e++) g_keys[gbase + e] = v[e];
}

// ---------------------------------------------------------------------------
// Kernel B (FUSED): bitonic merge (k=4096, 8192) + block-parallel kept-list
// greedy, one block of 1024 threads. Sorted boxes/areas/sidx live in SHARED
// memory (192KB dynamic; the 64KB merge key workspace aliases the boxes
// region — keys are register-resident when it gets overwritten).
// Greedy batch: 2 barriers (ballots -> resolve+append by warp 0 -> next).
// ---------------------------------------------------------------------------
__global__ __launch_bounds__(MT, 1)
void mg_kernel(const float4* __restrict__ rois, float* __restrict__ out) {
  extern __shared__ unsigned char blob[];
  u64*    sk     = reinterpret_cast<u64*>(blob);                  // [0,64K)
  float4* sboxes = reinterpret_cast<float4*>(blob);               // [0,128K)
  float*  sarea  = reinterpret_cast<float*>(blob + 131072);       // [128K,160K)
  int*    ssidx  = reinterpret_cast<int*>(blob + 163840);         // [160K,192K)

  __shared__ float4   kb[MAXO + 32];
  __shared__ float    ka[MAXO + 32];
  __shared__ unsigned supb[32], Sball[32];
  __shared__ int      Ksh;

  const int tid  = threadIdx.x;
  const int w    = tid >> 5;
  const int lane = tid & 31;
  const int base = tid * 8;
  const unsigned FULL = 0xFFFFFFFFu;

  if (tid < MAXO) out[tid] = -1.0f;

  // ---- merge phases k = 4096, 8192 ----
  u64 v[8];
#pragma unroll
  for (int e = 0; e < 8; e++) v[e] = g_keys[base + e];

  for (int k = 2 * CH; k <= NN; k <<= 1) {
    const bool up = ((base & k) == 0);
    int jj = k >> 1;
#pragma unroll
    for (int e = 0; e < 8; e++) sk[base + e] = v[e];
    __syncthreads();
    for (; jj >= 256; jj >>= 1) {
      for (int pp = tid; pp < NN / 2; pp += MT) {
        int p = ((pp & ~(jj - 1)) << 1) | (pp & (jj - 1));
        int q = p | jj;
        bool u2 = ((p & k) == 0);
        u64 a = sk[p], b = sk[q];
        if ((a > b) == u2) { sk[p] = b; sk[q] = a; }
      }
      __syncthreads();
    }
#pragma unroll
    for (int e = 0; e < 8; e++) v[e] = sk[base + e];
    for (; jj >= 8; jj >>= 1) {
      int s = jj >> 3;
      bool takemin = (((tid & s) == 0) == up);
#pragma unroll
      for (int e = 0; e < 8; e++) {
        u64 o  = __shfl_xor_sync(FULL, v[e], s);
        u64 mn = (v[e] < o) ? v[e] : o;
        u64 mx = (v[e] < o) ? o : v[e];
        v[e] = takemin ? mn : mx;
      }
    }
#pragma unroll
    for (int j2 = 4; j2; j2 >>= 1)
#pragma unroll
      for (int e = 0; e < 8; e++) { int e2 = e ^ j2; if (e2 > e) cmpex(v[e], v[e2], up); }
  }
  __syncthreads();   // all sk reads done before aliasing overwrite

  // ---- emit sorted data into shared (aliases dead key workspace) ----
#pragma unroll
  for (int e = 0; e < 8; e++) {
    int p  = base + e;
    int id = (int)(unsigned)(v[e] & 0xFFFFFFFFull);
    float4 bb = rois[id];
    sboxes[p] = bb;
    sarea[p]  = __fmul_rn(__fsub_rn(bb.z, bb.x), __fsub_rn(bb.w, bb.y));
    ssidx[p]  = id;
  }
  __syncthreads();

  // ---- block-parallel kept-list greedy, 2 barriers per batch ----
  int K = 0;
  for (int p = 0; p < NN && K < MAXO; p += 32) {
    const float4 b = sboxes[p + lane];   // broadcast LDS
    const float  a = sarea[p + lane];

    bool sup = false;
    for (int k = w; k < K; k += 32)
      sup |= iou_gt(b, a, kb[k], ka[k]);
    unsigned sb = __ballot_sync(FULL, sup);
    unsigned rb = __ballot_sync(FULL, iou_gt(b, a, sboxes[p + w], sarea[p + w]));
    if (lane == 0) { supb[w] = sb; Sball[w] = rb; }
    __syncthreads();

    if (w == 0) {
      unsigned so = supb[lane];
#pragma unroll
      for (int off = 16; off; off >>= 1) so |= __shfl_xor_sync(FULL, so, off);
      unsigned kept = 0;
      if (lane == 0) {
        unsigned rest = ~so;
        while (rest) {
          int m = __ffs(rest) - 1;
          kept |= 1u << m;
          rest &= ~(Sball[m] | (1u << m));   // extra low bits harmless
        }
      }
      kept = __shfl_sync(FULL, kept, 0);
      if ((kept >> lane) & 1u) {
        int slot = K + __popc(kept & ((1u << lane) - 1u));
        kb[slot] = b; ka[slot] = a;
        if (slot < MAXO) out[slot] = (float)ssidx[p + lane];
      }
      if (lane == 0) Ksh = K + __popc(kept);
    }
    __syncthreads();
    K = Ksh;
  }
}

// ---------------------------------------------------------------------------
extern "C" void kernel_launch(void* const* d_in, const int* in_sizes, int n_in,
                              void* d_out, int out_size) {
  const void* a0 = d_in[0];
  const void* a1 = d_in[1];
  const float4* rois;
  const float*  scores;
  if (in_sizes[0] >= in_sizes[1]) { rois = (const float4*)a0; scores = (const float*)a1; }
  else                            { rois = (const float4*)a1; scores = (const float*)a0; }

  const int mg_smem = 196608;   // 192KB: boxes(128K) + area(32K) + sidx(32K)
  cudaFuncSetAttribute(mg_kernel, cudaFuncAttributeMaxDynamicSharedMemorySize,
                       mg_smem);

  chunk_sort<<<NN / CH, CT>>>(scores);
  mg_kernel<<<1, MT, mg_smem>>>(rois, (float*)d_out);
}